// round 16
// baseline (speedup 1.0000x reference)
#include <cuda_runtime.h>
#include <cuda_bf16.h>
#include <math.h>
#include <stdint.h>
#include <string.h>

#define HW 4096
#define CH 256
#define NB 4
#define NBC (NB*CH)
#define KSPLIT 4

typedef __nv_bfloat16 bf16;

// ---- scratch (static device globals; no allocation) ----
__device__ float g_mean[2 * NBC];
__device__ float g_rstd[2 * NBC];
__device__ bf16 g_Qh[(size_t)NB * HW * CH];
__device__ bf16 g_Ql[(size_t)NB * HW * CH];
__device__ bf16 g_Kh[(size_t)NB * HW * CH];
__device__ bf16 g_Kl[(size_t)NB * HW * CH];
// B for GEMM2: rows 0..255 = V^T [c][p], rows 256..511 = (V^2)^T
__device__ bf16 g_VBh[(size_t)NB * 512 * HW];
__device__ bf16 g_VBl[(size_t)NB * 512 * HW];
__device__ float g_S[(size_t)NB * HW * HW];
// per-(row, n-tile) softmax partials from GEMM1 epilogue (32 tiles/row)
__device__ float g_tmax[(size_t)NB * HW * 32];
__device__ float g_tsum[(size_t)NB * HW * 32];
__device__ float g_rmax[(size_t)NB * HW];
__device__ float g_rinv[(size_t)NB * HW];
// split-K partials: [slice][b][q][0:256)=mean, [256:512)=sec
__device__ float g_ms[(size_t)KSPLIT * NB * HW * 512];

// ---------------- helpers ----------------
__device__ __forceinline__ uint32_t smem_u32(const void* p) {
    return (uint32_t)__cvta_generic_to_shared(p);
}
__device__ __forceinline__ void cpa16(uint32_t dst, const void* src) {
    asm volatile("cp.async.cg.shared.global [%0], [%1], 16;" :: "r"(dst), "l"(src));
}
__device__ __forceinline__ void cpa_commit() { asm volatile("cp.async.commit_group;"); }

__device__ __forceinline__ unsigned long long ffma2(unsigned long long a,
                                                    unsigned long long b,
                                                    unsigned long long c) {
    unsigned long long d;
    asm("fma.rn.f32x2 %0, %1, %2, %3;" : "=l"(d) : "l"(a), "l"(b), "l"(c));
    return d;
}
__device__ __forceinline__ unsigned long long fpack2(float x) {
    unsigned long long d;
    unsigned int xi = __float_as_uint(x);
    asm("mov.b64 %0, {%1, %1};" : "=l"(d) : "r"(xi));
    return d;
}
__device__ __forceinline__ float2 funpack(unsigned long long v) {
    unsigned int lo, hi;
    asm("mov.b64 {%0, %1}, %2;" : "=r"(lo), "=r"(hi) : "l"(v));
    float2 r; r.x = __uint_as_float(lo); r.y = __uint_as_float(hi);
    return r;
}
__device__ __forceinline__ void ldsm4(uint32_t& r0, uint32_t& r1, uint32_t& r2,
                                      uint32_t& r3, uint32_t a) {
    asm volatile("ldmatrix.sync.aligned.m8n8.x4.shared.b16 {%0,%1,%2,%3}, [%4];"
                 : "=r"(r0), "=r"(r1), "=r"(r2), "=r"(r3) : "r"(a));
}
__device__ __forceinline__ void mma16816(float* c, const uint32_t* a, const uint32_t* b) {
    asm volatile("mma.sync.aligned.m16n8k16.row.col.f32.bf16.bf16.f32 "
                 "{%0,%1,%2,%3}, {%4,%5,%6,%7}, {%8,%9}, {%0,%1,%2,%3};"
                 : "+f"(c[0]), "+f"(c[1]), "+f"(c[2]), "+f"(c[3])
                 : "r"(a[0]), "r"(a[1]), "r"(a[2]), "r"(a[3]),
                   "r"(b[0]), "r"(b[1]));
}
__device__ __forceinline__ void split_bf(float x, bf16& h, bf16& l) {
    h = __float2bfloat16_rn(x);
    l = __float2bfloat16_rn(x - __bfloat162float(h));
}
__device__ __forceinline__ uint32_t pack_bf(bf16 a, bf16 b) {
    __nv_bfloat162 t; t.x = a; t.y = b;
    uint32_t u; memcpy(&u, &t, 4); return u;
}

// =====================================================================
// Stage 1: per-(b,c) mean / rstd (ddof=1, +1e-5)
// =====================================================================
__global__ void stats_kernel(const float* __restrict__ content,
                             const float* __restrict__ style) {
    int id = blockIdx.x;
    const float* base = (id < NBC ? content : style) + (size_t)(id & (NBC - 1)) * HW;
    float s = 0.f, s2 = 0.f;
    const float4* b4 = (const float4*)base;
    for (int i = threadIdx.x; i < HW / 4; i += 256) {
        float4 v = b4[i];
        s  += v.x + v.y + v.z + v.w;
        s2 += v.x * v.x + v.y * v.y + v.z * v.z + v.w * v.w;
    }
    #pragma unroll
    for (int o = 16; o; o >>= 1) {
        s  += __shfl_xor_sync(~0u, s, o);
        s2 += __shfl_xor_sync(~0u, s2, o);
    }
    __shared__ float sh[8][2];
    int w = threadIdx.x >> 5, l = threadIdx.x & 31;
    if (l == 0) { sh[w][0] = s; sh[w][1] = s2; }
    __syncthreads();
    if (threadIdx.x == 0) {
        s = 0.f; s2 = 0.f;
        #pragma unroll
        for (int i = 0; i < 8; i++) { s += sh[i][0]; s2 += sh[i][1]; }
        float m   = s / (float)HW;
        float var = (s2 - (float)HW * m * m) / (float)(HW - 1);
        g_mean[id] = m;
        g_rstd[id] = rsqrtf(var + 1e-5f);
    }
}

// =====================================================================
// Stage 2: Q/K/V 1x1 convs (f32x2 inner loop); split-bf16 outputs.
// =====================================================================
__global__ __launch_bounds__(256) void qkv_gemm(
    const float* __restrict__ content, const float* __restrict__ style,
    const float* __restrict__ Wf, const float* __restrict__ bfb,
    const float* __restrict__ Wg, const float* __restrict__ bg,
    const float* __restrict__ Wh, const float* __restrict__ bh)
{
    int z = blockIdx.z;
    int mat = z % 3, b = z / 3;
    const float *X, *W, *bias;
    int soff;
    if (mat == 0)      { X = content; W = Wf; bias = bfb; soff = 0;   }
    else if (mat == 1) { X = style;   W = Wg; bias = bg;  soff = NBC; }
    else               { X = style;   W = Wh; bias = bh;  soff = -1;  }
    X += (size_t)b * CH * HW;
    int p0 = blockIdx.x * 128, o0 = blockIdx.y * 64;

    __shared__ float Xs[32][132];
    __shared__ float Ws[64][36];

    int tid = threadIdx.x;
    int tx  = tid & 15, ty = tid >> 4;
    unsigned long long acc2[4][4];
    #pragma unroll
    for (int u = 0; u < 4; u++)
        #pragma unroll
        for (int v = 0; v < 4; v++) acc2[u][v] = 0ull;

    for (int c0 = 0; c0 < CH; c0 += 32) {
        __syncthreads();
        #pragma unroll
        for (int r = 0; r < 4; r++) {
            int e = tid + 256 * r;
            int row = e >> 5, c4 = e & 31;
            float4 v = *(const float4*)(X + (size_t)(c0 + row) * HW + p0 + c4 * 4);
            if (soff >= 0) {
                float m  = g_mean[soff + b * CH + c0 + row];
                float rs = g_rstd[soff + b * CH + c0 + row];
                v.x = (v.x - m) * rs; v.y = (v.y - m) * rs;
                v.z = (v.z - m) * rs; v.w = (v.w - m) * rs;
            }
            *(float4*)&Xs[row][c4 * 4] = v;
        }
        #pragma unroll
        for (int r = 0; r < 2; r++) {
            int e = tid + 256 * r;
            int row = e >> 3, c4 = e & 7;
            *(float4*)&Ws[row][c4 * 4] =
                *(const float4*)(W + (size_t)(o0 + row) * CH + c0 + c4 * 4);
        }
        __syncthreads();
        #pragma unroll
        for (int cc = 0; cc < 32; cc++) {
            ulonglong2 x01 = *(ulonglong2*)&Xs[cc][tx * 8];
            ulonglong2 x23 = *(ulonglong2*)&Xs[cc][tx * 8 + 4];
            unsigned long long xv2[4] = {x01.x, x01.y, x23.x, x23.y};
            unsigned long long wp0 = fpack2(Ws[ty * 4 + 0][cc]);
            unsigned long long wp1 = fpack2(Ws[ty * 4 + 1][cc]);
            unsigned long long wp2 = fpack2(Ws[ty * 4 + 2][cc]);
            unsigned long long wp3 = fpack2(Ws[ty * 4 + 3][cc]);
            #pragma unroll
            for (int u = 0; u < 4; u++) {
                acc2[u][0] = ffma2(xv2[u], wp0, acc2[u][0]);
                acc2[u][1] = ffma2(xv2[u], wp1, acc2[u][1]);
                acc2[u][2] = ffma2(xv2[u], wp2, acc2[u][2]);
                acc2[u][3] = ffma2(xv2[u], wp3, acc2[u][3]);
            }
        }
    }
    float bv[4] = {bias[o0 + ty * 4 + 0], bias[o0 + ty * 4 + 1],
                   bias[o0 + ty * 4 + 2], bias[o0 + ty * 4 + 3]};
    float accv[8][4];
    #pragma unroll
    for (int u = 0; u < 4; u++)
        #pragma unroll
        for (int v = 0; v < 4; v++) {
            float2 t = funpack(acc2[u][v]);
            accv[2 * u][v] = t.x + bv[v];
            accv[2 * u + 1][v] = t.y + bv[v];
        }

    if (mat < 2) {
        bf16* oh = (mat ? g_Kh : g_Qh) + (size_t)b * HW * CH;
        bf16* ol = (mat ? g_Kl : g_Ql) + (size_t)b * HW * CH;
        #pragma unroll
        for (int u = 0; u < 8; u++) {
            size_t ix = (size_t)(p0 + tx * 8 + u) * CH + o0 + ty * 4;
            bf16 h[4], l[4];
            #pragma unroll
            for (int v = 0; v < 4; v++) split_bf(accv[u][v], h[v], l[v]);
            *(uint2*)(oh + ix) = *(uint2*)h;
            *(uint2*)(ol + ix) = *(uint2*)l;
        }
    } else {
        size_t vb = (size_t)b * 512 * HW;
        #pragma unroll
        for (int v = 0; v < 4; v++) {
            int c = o0 + ty * 4 + v;
            size_t ix  = vb + (size_t)c * HW + p0 + tx * 8;
            size_t ix2 = vb + (size_t)(c + 256) * HW + p0 + tx * 8;
            bf16 hv[8], lv[8], h2[8], l2[8];
            #pragma unroll
            for (int u = 0; u < 8; u++) {
                float x = accv[u][v];
                split_bf(x, hv[u], lv[u]);
                split_bf(x * x, h2[u], l2[u]);
            }
            *(uint4*)(g_VBh + ix)  = *(uint4*)hv;
            *(uint4*)(g_VBl + ix)  = *(uint4*)lv;
            *(uint4*)(g_VBh + ix2) = *(uint4*)h2;
            *(uint4*)(g_VBl + ix2) = *(uint4*)l2;
        }
    }
}

// =====================================================================
// GEMM1: S = (Qh+Ql).(Kh+Kl)^T, 128x128 block, 2-stage, 2 CTAs/SM.
// Fused epilogue: per-(row, n-tile) max and sumexp partials.
// =====================================================================
#define PADH  40                    // halves per smem row (32 data + 8 pad)
#define TILEB (128 * PADH * 2)      // 10240 B per matrix tile
#define STAGEB (4 * TILEB)          // 40960 B
#define GSMEM (2 * STAGEB)          // 81920 B

__global__ __launch_bounds__(256, 2) void mma_gemm(
    const bf16* __restrict__ Ah_, const bf16* __restrict__ Al_,
    const bf16* __restrict__ Bh_, const bf16* __restrict__ Bl_,
    float* __restrict__ C_)
{
    extern __shared__ char gsm[];
    uint32_t smb = smem_u32(gsm);
    const int K = CH;
    int b = blockIdx.z, m0 = blockIdx.y * 128, n0 = blockIdx.x * 128;
    int tid = threadIdx.x, lane = tid & 31, wid = tid >> 5;
    int wm = wid & 3, wn = wid >> 2;

    const bf16* gsrc[4];
    gsrc[0] = Ah_ + (size_t)b * HW * CH + (size_t)m0 * K;
    gsrc[1] = Al_ + (size_t)b * HW * CH + (size_t)m0 * K;
    gsrc[2] = Bh_ + (size_t)b * HW * CH + (size_t)n0 * K;
    gsrc[3] = Bl_ + (size_t)b * HW * CH + (size_t)n0 * K;

    float Cf[2][8][4];
    #pragma unroll
    for (int mi = 0; mi < 2; mi++)
        #pragma unroll
        for (int nj = 0; nj < 8; nj++)
            #pragma unroll
            for (int q = 0; q < 4; q++) Cf[mi][nj][q] = 0.f;

    uint32_t aoff[2], boff[4];
    #pragma unroll
    for (int mi = 0; mi < 2; mi++)
        aoff[mi] = ((uint32_t)(wm * 32 + mi * 16 + (lane & 15)) * PADH +
                    ((lane >> 4) << 3)) * 2u;
    #pragma unroll
    for (int njp = 0; njp < 4; njp++)
        boff[njp] = ((uint32_t)(wn * 64 + njp * 16 + (lane & 7) + ((lane >> 4) << 3)) * PADH +
                     (((lane >> 3) & 1) << 3)) * 2u;

    const int nch = K >> 5;   // 8

    auto load_chunk = [&](int ch) {
        int k0 = ch << 5;
        uint32_t dbase = smb + (uint32_t)(ch & 1) * STAGEB;
        #pragma unroll
        for (int t = 0; t < 8; t++) {
            int e = tid + (t << 8);
            int matq = e >> 9, rem = e & 511;
            int row = rem >> 2, cc = rem & 3;
            cpa16(dbase + (uint32_t)matq * TILEB + (uint32_t)(row * PADH) * 2u + cc * 16,
                  gsrc[matq] + (size_t)row * K + k0 + cc * 8);
        }
        cpa_commit();
    };

    load_chunk(0);
    load_chunk(1);
    for (int ch = 0; ch < nch; ch++) {
        if (ch + 1 < nch) asm volatile("cp.async.wait_group 1;");
        else              asm volatile("cp.async.wait_group 0;");
        __syncthreads();

        uint32_t sbase = smb + (uint32_t)(ch & 1) * STAGEB;
        #pragma unroll
        for (int ks = 0; ks < 2; ks++) {
            uint32_t kb = sbase + (ks << 5);
            uint32_t Afh[2][4], Afl[2][4], Bfh[8][2], Bfl[8][2];
            #pragma unroll
            for (int mi = 0; mi < 2; mi++) {
                ldsm4(Afh[mi][0], Afh[mi][1], Afh[mi][2], Afh[mi][3], kb + aoff[mi]);
                ldsm4(Afl[mi][0], Afl[mi][1], Afl[mi][2], Afl[mi][3],
                      kb + TILEB + aoff[mi]);
            }
            #pragma unroll
            for (int njp = 0; njp < 4; njp++) {
                uint32_t r0, r1, r2, r3;
                ldsm4(r0, r1, r2, r3, kb + 2 * TILEB + boff[njp]);
                Bfh[2 * njp][0] = r0; Bfh[2 * njp][1] = r1;
                Bfh[2 * njp + 1][0] = r2; Bfh[2 * njp + 1][1] = r3;
                ldsm4(r0, r1, r2, r3, kb + 3 * TILEB + boff[njp]);
                Bfl[2 * njp][0] = r0; Bfl[2 * njp][1] = r1;
                Bfl[2 * njp + 1][0] = r2; Bfl[2 * njp + 1][1] = r3;
            }
            #pragma unroll
            for (int mi = 0; mi < 2; mi++)
                #pragma unroll
                for (int nj = 0; nj < 8; nj++) {
                    mma16816(Cf[mi][nj], Afh[mi], Bfh[nj]);
                    mma16816(Cf[mi][nj], Afh[mi], Bfl[nj]);
                    mma16816(Cf[mi][nj], Afl[mi], Bfh[nj]);
                }
        }
        __syncthreads();
        if (ch + 2 < nch) load_chunk(ch + 2);
    }

    // ---- store S tile ----
    float* Cb = C_ + (size_t)b * HW * HW + (size_t)m0 * HW + n0;
    int r0 = wm * 32 + (lane >> 2);
    int c0 = wn * 64 + ((lane & 3) << 1);
    #pragma unroll
    for (int mi = 0; mi < 2; mi++)
        #pragma unroll
        for (int nj = 0; nj < 8; nj++) {
            int r = r0 + mi * 16, c = c0 + nj * 8;
            *(float2*)&Cb[(size_t)r * HW + c] =
                make_float2(Cf[mi][nj][0], Cf[mi][nj][1]);
            *(float2*)&Cb[(size_t)(r + 8) * HW + c] =
                make_float2(Cf[mi][nj][2], Cf[mi][nj][3]);
        }

    // ---- fused per-tile softmax partials (max, sumexp over 128 cols) ----
    __shared__ float sredm[128][2];
    __shared__ float sreds[128][2];
    float mx4[4];
    #pragma unroll
    for (int s = 0; s < 4; s++) {
        int mi = s >> 1, qb = (s & 1) * 2;
        float m = -1e30f;
        #pragma unroll
        for (int nj = 0; nj < 8; nj++)
            m = fmaxf(m, fmaxf(Cf[mi][nj][qb], Cf[mi][nj][qb + 1]));
        m = fmaxf(m, __shfl_xor_sync(~0u, m, 1));
        m = fmaxf(m, __shfl_xor_sync(~0u, m, 2));
        mx4[s] = m;
    }
    if ((lane & 3) == 0) {
        #pragma unroll
        for (int s = 0; s < 4; s++) {
            int rloc = r0 + (s >> 1) * 16 + (s & 1) * 8;
            sredm[rloc][wn] = mx4[s];
        }
    }
    __syncthreads();
    float rmx[4], sm4[4];
    #pragma unroll
    for (int s = 0; s < 4; s++) {
        int rloc = r0 + (s >> 1) * 16 + (s & 1) * 8;
        rmx[s] = fmaxf(sredm[rloc][0], sredm[rloc][1]);
        int mi = s >> 1, qb = (s & 1) * 2;
        float sum = 0.f;
        #pragma unroll
        for (int nj = 0; nj < 8; nj++)
            sum += __expf(Cf[mi][nj][qb] - rmx[s]) +
                   __expf(Cf[mi][nj][qb + 1] - rmx[s]);
        sum += __shfl_xor_sync(~0u, sum, 1);
        sum += __shfl_xor_sync(~0u, sum, 2);
        sm4[s] = sum;
    }
    if ((lane & 3) == 0) {
        #pragma unroll
        for (int s = 0; s < 4; s++) {
            int rloc = r0 + (s >> 1) * 16 + (s & 1) * 8;
            sreds[rloc][wn] = sm4[s];
        }
    }
    __syncthreads();
    if (wn == 0 && (lane & 3) == 0) {
        #pragma unroll
        for (int s = 0; s < 4; s++) {
            int rloc = r0 + (s >> 1) * 16 + (s & 1) * 8;
            size_t ix = ((size_t)b * HW + m0 + rloc) * 32 + blockIdx.x;
            g_tmax[ix] = rmx[s];
            g_tsum[ix] = sreds[rloc][0] + sreds[rloc][1];
        }
    }
}

// =====================================================================
// Combine per-tile partials: rmax = max_t m_t; rinv = 1/Σ s_t exp(m_t−M)
// =====================================================================
__global__ __launch_bounds__(256) void rowfin_kernel() {
    int row = blockIdx.x * 8 + (threadIdx.x >> 5);   // global (b*HW + q)
    int lane = threadIdx.x & 31;
    float m = g_tmax[(size_t)row * 32 + lane];
    float s = g_tsum[(size_t)row * 32 + lane];
    float M = m;
    #pragma unroll
    for (int o = 16; o; o >>= 1) M = fmaxf(M, __shfl_xor_sync(~0u, M, o));
    float v = s * __expf(m - M);
    #pragma unroll
    for (int o = 16; o; o >>= 1) v += __shfl_xor_sync(~0u, v, o);
    if (lane == 0) {
        g_rmax[row] = M;
        g_rinv[row] = 1.0f / v;
    }
}

// =====================================================================
// GEMM2 with fused softmax A-path, TWO n-tiles per block (128x256),
// 2-stage pipeline.
// =====================================================================
#define KLEN (HW / KSPLIT)          // 1024
#define STAGE2B (6 * TILEB)         // 61440
#define GSMEM2 (2 * STAGE2B)        // 122880

__global__ __launch_bounds__(256, 1) void gemm2_mma() {
    extern __shared__ char gsm[];
    uint32_t smb = smem_u32(gsm);
    int b = blockIdx.z / KSPLIT, slice = blockIdx.z % KSPLIT;
    int koff = slice * KLEN;
    int m0 = blockIdx.y * 128, n0 = blockIdx.x * 256;
    int tid = threadIdx.x, lane = tid & 31, wid = tid >> 5;
    int wm = wid & 3, wn = wid >> 2;

    // A (S) per-thread: row r, 16-col group cg
    int r = tid >> 1, cg = (tid & 1) * 16;
    const float* Arow = g_S + ((size_t)(b * HW + m0 + r)) * HW + koff + cg;
    float rmax = g_rmax[(size_t)b * HW + m0 + r];
    float rinv = g_rinv[(size_t)b * HW + m0 + r];
    uint32_t ah_dst = smb + (uint32_t)(r * PADH + cg) * 2u;

    const bf16* Bh = g_VBh + (size_t)b * 512 * HW + (size_t)n0 * HW + koff;
    const bf16* Bl = g_VBl + (size_t)b * 512 * HW + (size_t)n0 * HW + koff;

    float Cf[2][2][8][4];   // [ntile][mi][nj][q]
    #pragma unroll
    for (int nt = 0; nt < 2; nt++)
        #pragma unroll
        for (int mi = 0; mi < 2; mi++)
            #pragma unroll
            for (int nj = 0; nj < 8; nj++)
                #pragma unroll
                for (int q = 0; q < 4; q++) Cf[nt][mi][nj][q] = 0.f;

    uint32_t aoff[2], boff[4];
    #pragma unroll
    for (int mi = 0; mi < 2; mi++)
        aoff[mi] = ((uint32_t)(wm * 32 + mi * 16 + (lane & 15)) * PADH +
                    ((lane >> 4) << 3)) * 2u;
    #pragma unroll
    for (int njp = 0; njp < 4; njp++)
        boff[njp] = ((uint32_t)(wn * 64 + njp * 16 + (lane & 7) + ((lane >> 4) << 3)) * PADH +
                     (((lane >> 3) & 1) << 3)) * 2u;

    const int nch = KLEN >> 5;   // 32

    // B loader: 4 tiles (nt0 hi, nt0 lo, nt1 hi, nt1 lo), 2048 pieces
    auto loadB = [&](int ch) {
        int k0 = ch << 5;
        uint32_t dbase = smb + (uint32_t)(ch & 1) * STAGE2B + 2 * TILEB;
        #pragma unroll
        for (int t = 0; t < 8; t++) {
            int e = tid + (t << 8);
            int matq = e >> 9, rem = e & 511;   // matq: nt*2 + hl
            int nt = matq >> 1, hl = matq & 1;
            int row = rem >> 2, cc = rem & 3;
            const bf16* src = (hl ? Bl : Bh) + (size_t)(nt * 128 + row) * HW + k0 + cc * 8;
            cpa16(dbase + (uint32_t)matq * TILEB +
                      (uint32_t)(row * PADH) * 2u + cc * 16, src);
        }
        cpa_commit();
    };

    float4 pf[4];
    auto loadS = [&](int ch) {
        #pragma unroll
        for (int j = 0; j < 4; j++)
            pf[j] = *(const float4*)(Arow + (ch << 5) + j * 4);
    };
    auto storeA = [&](int st) {
        uint32_t h8[8], l8[8];
        #pragma unroll
        for (int j = 0; j < 4; j++) {
            float4 v = pf[j];
            float p0v = __expf(v.x - rmax) * rinv;
            float p1v = __expf(v.y - rmax) * rinv;
            float p2v = __expf(v.z - rmax) * rinv;
            float p3v = __expf(v.w - rmax) * rinv;
            bf16 h0, l0, h1, l1, h2, l2, h3, l3;
            split_bf(p0v, h0, l0); split_bf(p1v, h1, l1);
            split_bf(p2v, h2, l2); split_bf(p3v, h3, l3);
            h8[2 * j]     = pack_bf(h0, h1);
            h8[2 * j + 1] = pack_bf(h2, h3);
            l8[2 * j]     = pack_bf(l0, l1);
            l8[2 * j + 1] = pack_bf(l2, l3);
        }
        uint32_t dst = ah_dst + (uint32_t)st * STAGE2B;
        asm volatile("st.shared.v4.b32 [%0], {%1,%2,%3,%4};"
                     :: "r"(dst), "r"(h8[0]), "r"(h8[1]), "r"(h8[2]), "r"(h8[3]));
        asm volatile("st.shared.v4.b32 [%0], {%1,%2,%3,%4};"
                     :: "r"(dst + 16), "r"(h8[4]), "r"(h8[5]), "r"(h8[6]), "r"(h8[7]));
        asm volatile("st.shared.v4.b32 [%0], {%1,%2,%3,%4};"
                     :: "r"(dst + TILEB), "r"(l8[0]), "r"(l8[1]), "r"(l8[2]), "r"(l8[3]));
        asm volatile("st.shared.v4.b32 [%0], {%1,%2,%3,%4};"
                     :: "r"(dst + TILEB + 16), "r"(l8[4]), "r"(l8[5]), "r"(l8[6]), "r"(l8[7]));
    };

    loadS(0);
    loadB(0);
    for (int ch = 0; ch < nch; ch++) {
        if (ch + 1 < nch) loadB(ch + 1);
        storeA(ch & 1);
        if (ch + 1 < nch) loadS(ch + 1);
        if (ch + 1 < nch) asm volatile("cp.async.wait_group 1;");
        else              asm volatile("cp.async.wait_group 0;");
        __syncthreads();

        uint32_t sbase = smb + (uint32_t)(ch & 1) * STAGE2B;
        #pragma unroll
        for (int ks = 0; ks < 2; ks++) {
            uint32_t kb = sbase + (ks << 5);
            uint32_t Afh[2][4], Afl[2][4];
            #pragma unroll
            for (int mi = 0; mi < 2; mi++) {
                ldsm4(Afh[mi][0], Afh[mi][1], Afh[mi][2], Afh[mi][3], kb + aoff[mi]);
                ldsm4(Afl[mi][0], Afl[mi][1], Afl[mi][2], Afl[mi][3],
                      kb + TILEB + aoff[mi]);
            }
            #pragma unroll
            for (int nt = 0; nt < 2; nt++) {
                uint32_t bh_base = kb + (uint32_t)(2 + 2 * nt) * TILEB;
                uint32_t Bfh[8][2], Bfl[8][2];
                #pragma unroll
                for (int njp = 0; njp < 4; njp++) {
                    uint32_t q0, q1, q2, q3;
                    ldsm4(q0, q1, q2, q3, bh_base + boff[njp]);
                    Bfh[2 * njp][0] = q0; Bfh[2 * njp][1] = q1;
                    Bfh[2 * njp + 1][0] = q2; Bfh[2 * njp + 1][1] = q3;
                    ldsm4(q0, q1, q2, q3, bh_base + TILEB + boff[njp]);
                    Bfl[2 * njp][0] = q0; Bfl[2 * njp][1] = q1;
                    Bfl[2 * njp + 1][0] = q2; Bfl[2 * njp + 1][1] = q3;
                }
                #pragma unroll
                for (int mi = 0; mi < 2; mi++)
                    #pragma unroll
                    for (int nj = 0; nj < 8; nj++) {
                        mma16816(Cf[nt][mi][nj], Afh[mi], Bfh[nj]);
                        mma16816(Cf[nt][mi][nj], Afh[mi], Bfl[nj]);
                        mma16816(Cf[nt][mi][nj], Afl[mi], Bfh[nj]);
                    }
            }
        }
        __syncthreads();
    }

    int r0 = wm * 32 + (lane >> 2);
    int c0 = wn * 64 + ((lane & 3) << 1);
    #pragma unroll
    for (int nt = 0; nt < 2; nt++) {
        float* Cb = g_ms + ((size_t)slice * NB + b) * HW * 512 +
                    (size_t)m0 * 512 + n0 + nt * 128;
        #pragma unroll
        for (int mi = 0; mi < 2; mi++)
            #pragma unroll
            for (int nj = 0; nj < 8; nj++) {
                int rr = r0 + mi * 16, c = c0 + nj * 8;
                *(float2*)&Cb[(size_t)rr * 512 + c] =
                    make_float2(Cf[nt][mi][nj][0], Cf[nt][mi][nj][1]);
                *(float2*)&Cb[(size_t)(rr + 8) * 512 + c] =
                    make_float2(Cf[nt][mi][nj][2], Cf[nt][mi][nj][3]);
            }
    }
}

// =====================================================================
// Epilogue: sum KSPLIT partials of g_ms, transpose, final outputs.
// =====================================================================
#define EPSM (2 * 256 * 33 * 4)
__global__ __launch_bounds__(256) void epilogue_kernel(
    const float* __restrict__ content, float* __restrict__ out) {
    extern __shared__ float esm[];
    float* ms = esm;              // [256][33]
    float* ss = esm + 256 * 33;
    int p0 = blockIdx.x * 32, b = blockIdx.y;
    int tid = threadIdx.x, w = tid >> 5, lane = tid & 31;
    #pragma unroll
    for (int it = 0; it < 8; it++) {
        int e = tid + (it << 8);
        int row = e >> 6;            // 0..31
        int c4 = (e & 63) << 2;      // 0..252
        float4 mv = make_float4(0.f, 0.f, 0.f, 0.f);
        float4 sv = make_float4(0.f, 0.f, 0.f, 0.f);
        #pragma unroll
        for (int sl = 0; sl < KSPLIT; sl++) {
            const float* src = g_ms +
                (((size_t)sl * NB + b) * HW + p0 + row) * 512;
            float4 t = *(const float4*)(src + c4);
            float4 u = *(const float4*)(src + 256 + c4);
            mv.x += t.x; mv.y += t.y; mv.z += t.z; mv.w += t.w;
            sv.x += u.x; sv.y += u.y; sv.z += u.z; sv.w += u.w;
        }
        ms[(c4 + 0) * 33 + row] = mv.x; ms[(c4 + 1) * 33 + row] = mv.y;
        ms[(c4 + 2) * 33 + row] = mv.z; ms[(c4 + 3) * 33 + row] = mv.w;
        ss[(c4 + 0) * 33 + row] = sv.x; ss[(c4 + 1) * 33 + row] = sv.y;
        ss[(c4 + 2) * 33 + row] = sv.z; ss[(c4 + 3) * 33 + row] = sv.w;
    }
    __syncthreads();
    const size_t TSZ = (size_t)NB * CH * HW;
    #pragma unroll 4
    for (int g = 0; g < 32; g++) {
        int c = w * 32 + g;
        float mean = ms[c * 33 + lane];
        float sec  = ss[c * 33 + lane];
        float sd   = sqrtf(fmaxf(sec - mean * mean, 0.f));
        size_t idx = ((size_t)b * CH + c) * HW + p0 + lane;
        float nc = (content[idx] - g_mean[b * CH + c]) * g_rstd[b * CH + c];
        out[idx]           = sd * nc + mean;
        out[idx + TSZ]     = mean;
        out[idx + 2 * TSZ] = sd;
    }
}

// =====================================================================
extern "C" void kernel_launch(void* const* d_in, const int* in_sizes, int n_in,
                              void* d_out, int out_size) {
    const float* content = (const float*)d_in[0];
    const float* style   = (const float*)d_in[1];
    const float* Wf = (const float*)d_in[2];
    const float* bfp = (const float*)d_in[3];
    const float* Wg = (const float*)d_in[4];
    const float* bg = (const float*)d_in[5];
    const float* Wh = (const float*)d_in[6];
    const float* bh = (const float*)d_in[7];
    float* out = (float*)d_out;

    static bool init = false;
    static bf16 *pQh, *pQl, *pKh, *pKl;
    static float *pS;
    if (!init) {
        cudaGetSymbolAddress((void**)&pQh, g_Qh);
        cudaGetSymbolAddress((void**)&pQl, g_Ql);
        cudaGetSymbolAddress((void**)&pKh, g_Kh);
        cudaGetSymbolAddress((void**)&pKl, g_Kl);
        cudaGetSymbolAddress((void**)&pS, g_S);
        cudaFuncSetAttribute(mma_gemm,
                             cudaFuncAttributeMaxDynamicSharedMemorySize, GSMEM);
        cudaFuncSetAttribute(gemm2_mma,
                             cudaFuncAttributeMaxDynamicSharedMemorySize, GSMEM2);
        cudaFuncSetAttribute(epilogue_kernel,
                             cudaFuncAttributeMaxDynamicSharedMemorySize, EPSM);
        init = true;
    }

    stats_kernel<<<2 * NBC, 256>>>(content, style);
    qkv_gemm<<<dim3(HW / 128, CH / 64, 3 * NB), 256>>>(content, style,
                                                       Wf, bfp, Wg, bg, Wh, bh);
    // GEMM1: S = Qn . Kn^T + fused per-tile softmax partials
    mma_gemm<<<dim3(HW / 128, HW / 128, NB), 256, GSMEM>>>(
        pQh, pQl, pKh, pKl, pS);
    rowfin_kernel<<<NB * HW / 8, 256>>>();
    // GEMM2: [mean|sec] = softmax(S) . [V^T ; V2^T]^T, fused exp A-path,
    // two n-tiles per block (A converted once, reused); 128x256 blocks.
    gemm2_mma<<<dim3(512 / 256, HW / 128, NB * KSPLIT), 256, GSMEM2>>>();
    epilogue_kernel<<<dim3(HW / 32, NB), 256, EPSM>>>(content, out);
}

// round 17
// speedup vs baseline: 1.0148x; 1.0148x over previous
#include <cuda_runtime.h>
#include <cuda_bf16.h>
#include <math.h>
#include <stdint.h>
#include <string.h>

#define HW 4096
#define CH 256
#define NB 4
#define NBC (NB*CH)
#define KSPLIT 4

typedef __nv_bfloat16 bf16;

// ---- scratch (static device globals; no allocation) ----
__device__ float g_mean[2 * NBC];
__device__ float g_rstd[2 * NBC];
__device__ bf16 g_Qh[(size_t)NB * HW * CH];
__device__ bf16 g_Ql[(size_t)NB * HW * CH];
__device__ bf16 g_Kh[(size_t)NB * HW * CH];
__device__ bf16 g_Kl[(size_t)NB * HW * CH];
// B for GEMM2: rows 0..255 = V^T [c][p], rows 256..511 = (V^2)^T
__device__ bf16 g_VBh[(size_t)NB * 512 * HW];
__device__ bf16 g_VBl[(size_t)NB * 512 * HW];
__device__ float g_S[(size_t)NB * HW * HW];
// per-(row, n-tile) softmax partials from GEMM1 epilogue (32 tiles/row)
__device__ float g_tmax[(size_t)NB * HW * 32];
__device__ float g_tsum[(size_t)NB * HW * 32];
__device__ float g_rmax[(size_t)NB * HW];
__device__ float g_rinv[(size_t)NB * HW];
// split-K partials: [slice][b][q][0:256)=mean, [256:512)=sec
__device__ float g_ms[(size_t)KSPLIT * NB * HW * 512];

// ---------------- helpers ----------------
__device__ __forceinline__ uint32_t smem_u32(const void* p) {
    return (uint32_t)__cvta_generic_to_shared(p);
}
__device__ __forceinline__ void cpa16(uint32_t dst, const void* src) {
    asm volatile("cp.async.cg.shared.global [%0], [%1], 16;" :: "r"(dst), "l"(src));
}
__device__ __forceinline__ void cpa_commit() { asm volatile("cp.async.commit_group;"); }

__device__ __forceinline__ unsigned long long ffma2(unsigned long long a,
                                                    unsigned long long b,
                                                    unsigned long long c) {
    unsigned long long d;
    asm("fma.rn.f32x2 %0, %1, %2, %3;" : "=l"(d) : "l"(a), "l"(b), "l"(c));
    return d;
}
__device__ __forceinline__ unsigned long long fpack2(float x) {
    unsigned long long d;
    unsigned int xi = __float_as_uint(x);
    asm("mov.b64 %0, {%1, %1};" : "=l"(d) : "r"(xi));
    return d;
}
__device__ __forceinline__ float2 funpack(unsigned long long v) {
    unsigned int lo, hi;
    asm("mov.b64 {%0, %1}, %2;" : "=r"(lo), "=r"(hi) : "l"(v));
    float2 r; r.x = __uint_as_float(lo); r.y = __uint_as_float(hi);
    return r;
}
__device__ __forceinline__ void ldsm4(uint32_t& r0, uint32_t& r1, uint32_t& r2,
                                      uint32_t& r3, uint32_t a) {
    asm volatile("ldmatrix.sync.aligned.m8n8.x4.shared.b16 {%0,%1,%2,%3}, [%4];"
                 : "=r"(r0), "=r"(r1), "=r"(r2), "=r"(r3) : "r"(a));
}
__device__ __forceinline__ void mma16816(float* c, const uint32_t* a, const uint32_t* b) {
    asm volatile("mma.sync.aligned.m16n8k16.row.col.f32.bf16.bf16.f32 "
                 "{%0,%1,%2,%3}, {%4,%5,%6,%7}, {%8,%9}, {%0,%1,%2,%3};"
                 : "+f"(c[0]), "+f"(c[1]), "+f"(c[2]), "+f"(c[3])
                 : "r"(a[0]), "r"(a[1]), "r"(a[2]), "r"(a[3]),
                   "r"(b[0]), "r"(b[1]));
}
__device__ __forceinline__ void split_bf(float x, bf16& h, bf16& l) {
    h = __float2bfloat16_rn(x);
    l = __float2bfloat16_rn(x - __bfloat162float(h));
}
__device__ __forceinline__ uint32_t pack_bf(bf16 a, bf16 b) {
    __nv_bfloat162 t; t.x = a; t.y = b;
    uint32_t u; memcpy(&u, &t, 4); return u;
}

// =====================================================================
// Stage 1: per-(b,c) mean / rstd (ddof=1, +1e-5)
// =====================================================================
__global__ void stats_kernel(const float* __restrict__ content,
                             const float* __restrict__ style) {
    int id = blockIdx.x;
    const float* base = (id < NBC ? content : style) + (size_t)(id & (NBC - 1)) * HW;
    float s = 0.f, s2 = 0.f;
    const float4* b4 = (const float4*)base;
    for (int i = threadIdx.x; i < HW / 4; i += 256) {
        float4 v = b4[i];
        s  += v.x + v.y + v.z + v.w;
        s2 += v.x * v.x + v.y * v.y + v.z * v.z + v.w * v.w;
    }
    #pragma unroll
    for (int o = 16; o; o >>= 1) {
        s  += __shfl_xor_sync(~0u, s, o);
        s2 += __shfl_xor_sync(~0u, s2, o);
    }
    __shared__ float sh[8][2];
    int w = threadIdx.x >> 5, l = threadIdx.x & 31;
    if (l == 0) { sh[w][0] = s; sh[w][1] = s2; }
    __syncthreads();
    if (threadIdx.x == 0) {
        s = 0.f; s2 = 0.f;
        #pragma unroll
        for (int i = 0; i < 8; i++) { s += sh[i][0]; s2 += sh[i][1]; }
        float m   = s / (float)HW;
        float var = (s2 - (float)HW * m * m) / (float)(HW - 1);
        g_mean[id] = m;
        g_rstd[id] = rsqrtf(var + 1e-5f);
    }
}

// =====================================================================
// Stage 2: Q/K/V 1x1 convs (f32x2 inner loop); split-bf16 outputs.
// =====================================================================
__global__ __launch_bounds__(256) void qkv_gemm(
    const float* __restrict__ content, const float* __restrict__ style,
    const float* __restrict__ Wf, const float* __restrict__ bfb,
    const float* __restrict__ Wg, const float* __restrict__ bg,
    const float* __restrict__ Wh, const float* __restrict__ bh)
{
    int z = blockIdx.z;
    int mat = z % 3, b = z / 3;
    const float *X, *W, *bias;
    int soff;
    if (mat == 0)      { X = content; W = Wf; bias = bfb; soff = 0;   }
    else if (mat == 1) { X = style;   W = Wg; bias = bg;  soff = NBC; }
    else               { X = style;   W = Wh; bias = bh;  soff = -1;  }
    X += (size_t)b * CH * HW;
    int p0 = blockIdx.x * 128, o0 = blockIdx.y * 64;

    __shared__ float Xs[32][132];
    __shared__ float Ws[64][36];

    int tid = threadIdx.x;
    int tx  = tid & 15, ty = tid >> 4;
    unsigned long long acc2[4][4];
    #pragma unroll
    for (int u = 0; u < 4; u++)
        #pragma unroll
        for (int v = 0; v < 4; v++) acc2[u][v] = 0ull;

    for (int c0 = 0; c0 < CH; c0 += 32) {
        __syncthreads();
        #pragma unroll
        for (int r = 0; r < 4; r++) {
            int e = tid + 256 * r;
            int row = e >> 5, c4 = e & 31;
            float4 v = *(const float4*)(X + (size_t)(c0 + row) * HW + p0 + c4 * 4);
            if (soff >= 0) {
                float m  = g_mean[soff + b * CH + c0 + row];
                float rs = g_rstd[soff + b * CH + c0 + row];
                v.x = (v.x - m) * rs; v.y = (v.y - m) * rs;
                v.z = (v.z - m) * rs; v.w = (v.w - m) * rs;
            }
            *(float4*)&Xs[row][c4 * 4] = v;
        }
        #pragma unroll
        for (int r = 0; r < 2; r++) {
            int e = tid + 256 * r;
            int row = e >> 3, c4 = e & 7;
            *(float4*)&Ws[row][c4 * 4] =
                *(const float4*)(W + (size_t)(o0 + row) * CH + c0 + c4 * 4);
        }
        __syncthreads();
        #pragma unroll
        for (int cc = 0; cc < 32; cc++) {
            ulonglong2 x01 = *(ulonglong2*)&Xs[cc][tx * 8];
            ulonglong2 x23 = *(ulonglong2*)&Xs[cc][tx * 8 + 4];
            unsigned long long xv2[4] = {x01.x, x01.y, x23.x, x23.y};
            unsigned long long wp0 = fpack2(Ws[ty * 4 + 0][cc]);
            unsigned long long wp1 = fpack2(Ws[ty * 4 + 1][cc]);
            unsigned long long wp2 = fpack2(Ws[ty * 4 + 2][cc]);
            unsigned long long wp3 = fpack2(Ws[ty * 4 + 3][cc]);
            #pragma unroll
            for (int u = 0; u < 4; u++) {
                acc2[u][0] = ffma2(xv2[u], wp0, acc2[u][0]);
                acc2[u][1] = ffma2(xv2[u], wp1, acc2[u][1]);
                acc2[u][2] = ffma2(xv2[u], wp2, acc2[u][2]);
                acc2[u][3] = ffma2(xv2[u], wp3, acc2[u][3]);
            }
        }
    }
    float bv[4] = {bias[o0 + ty * 4 + 0], bias[o0 + ty * 4 + 1],
                   bias[o0 + ty * 4 + 2], bias[o0 + ty * 4 + 3]};
    float accv[8][4];
    #pragma unroll
    for (int u = 0; u < 4; u++)
        #pragma unroll
        for (int v = 0; v < 4; v++) {
            float2 t = funpack(acc2[u][v]);
            accv[2 * u][v] = t.x + bv[v];
            accv[2 * u + 1][v] = t.y + bv[v];
        }

    if (mat < 2) {
        bf16* oh = (mat ? g_Kh : g_Qh) + (size_t)b * HW * CH;
        bf16* ol = (mat ? g_Kl : g_Ql) + (size_t)b * HW * CH;
        #pragma unroll
        for (int u = 0; u < 8; u++) {
            size_t ix = (size_t)(p0 + tx * 8 + u) * CH + o0 + ty * 4;
            bf16 h[4], l[4];
            #pragma unroll
            for (int v = 0; v < 4; v++) split_bf(accv[u][v], h[v], l[v]);
            *(uint2*)(oh + ix) = *(uint2*)h;
            *(uint2*)(ol + ix) = *(uint2*)l;
        }
    } else {
        size_t vb = (size_t)b * 512 * HW;
        #pragma unroll
        for (int v = 0; v < 4; v++) {
            int c = o0 + ty * 4 + v;
            size_t ix  = vb + (size_t)c * HW + p0 + tx * 8;
            size_t ix2 = vb + (size_t)(c + 256) * HW + p0 + tx * 8;
            bf16 hv[8], lv[8], h2[8], l2[8];
            #pragma unroll
            for (int u = 0; u < 8; u++) {
                float x = accv[u][v];
                split_bf(x, hv[u], lv[u]);
                split_bf(x * x, h2[u], l2[u]);
            }
            *(uint4*)(g_VBh + ix)  = *(uint4*)hv;
            *(uint4*)(g_VBl + ix)  = *(uint4*)lv;
            *(uint4*)(g_VBh + ix2) = *(uint4*)h2;
            *(uint4*)(g_VBl + ix2) = *(uint4*)l2;
        }
    }
}

// =====================================================================
// GEMM1: S = (Qh+Ql).(Kh+Kl)^T, 128x128 block, 2-stage, 2 CTAs/SM.
// Fused epilogue: per-(row, n-tile) max and sumexp partials.
// =====================================================================
#define PADH  40                    // halves per smem row (32 data + 8 pad)
#define TILEB (128 * PADH * 2)      // 10240 B per matrix tile
#define STAGEB (4 * TILEB)          // 40960 B
#define GSMEM (2 * STAGEB)          // 81920 B

__global__ __launch_bounds__(256, 2) void mma_gemm(
    const bf16* __restrict__ Ah_, const bf16* __restrict__ Al_,
    const bf16* __restrict__ Bh_, const bf16* __restrict__ Bl_,
    float* __restrict__ C_)
{
    extern __shared__ char gsm[];
    uint32_t smb = smem_u32(gsm);
    const int K = CH;
    int b = blockIdx.z, m0 = blockIdx.y * 128, n0 = blockIdx.x * 128;
    int tid = threadIdx.x, lane = tid & 31, wid = tid >> 5;
    int wm = wid & 3, wn = wid >> 2;

    const bf16* gsrc[4];
    gsrc[0] = Ah_ + (size_t)b * HW * CH + (size_t)m0 * K;
    gsrc[1] = Al_ + (size_t)b * HW * CH + (size_t)m0 * K;
    gsrc[2] = Bh_ + (size_t)b * HW * CH + (size_t)n0 * K;
    gsrc[3] = Bl_ + (size_t)b * HW * CH + (size_t)n0 * K;

    float Cf[2][8][4];
    #pragma unroll
    for (int mi = 0; mi < 2; mi++)
        #pragma unroll
        for (int nj = 0; nj < 8; nj++)
            #pragma unroll
            for (int q = 0; q < 4; q++) Cf[mi][nj][q] = 0.f;

    uint32_t aoff[2], boff[4];
    #pragma unroll
    for (int mi = 0; mi < 2; mi++)
        aoff[mi] = ((uint32_t)(wm * 32 + mi * 16 + (lane & 15)) * PADH +
                    ((lane >> 4) << 3)) * 2u;
    #pragma unroll
    for (int njp = 0; njp < 4; njp++)
        boff[njp] = ((uint32_t)(wn * 64 + njp * 16 + (lane & 7) + ((lane >> 4) << 3)) * PADH +
                     (((lane >> 3) & 1) << 3)) * 2u;

    const int nch = K >> 5;   // 8

    auto load_chunk = [&](int ch) {
        int k0 = ch << 5;
        uint32_t dbase = smb + (uint32_t)(ch & 1) * STAGEB;
        #pragma unroll
        for (int t = 0; t < 8; t++) {
            int e = tid + (t << 8);
            int matq = e >> 9, rem = e & 511;
            int row = rem >> 2, cc = rem & 3;
            cpa16(dbase + (uint32_t)matq * TILEB + (uint32_t)(row * PADH) * 2u + cc * 16,
                  gsrc[matq] + (size_t)row * K + k0 + cc * 8);
        }
        cpa_commit();
    };

    load_chunk(0);
    load_chunk(1);
    for (int ch = 0; ch < nch; ch++) {
        if (ch + 1 < nch) asm volatile("cp.async.wait_group 1;");
        else              asm volatile("cp.async.wait_group 0;");
        __syncthreads();

        uint32_t sbase = smb + (uint32_t)(ch & 1) * STAGEB;
        #pragma unroll
        for (int ks = 0; ks < 2; ks++) {
            uint32_t kb = sbase + (ks << 5);
            uint32_t Afh[2][4], Afl[2][4], Bfh[8][2], Bfl[8][2];
            #pragma unroll
            for (int mi = 0; mi < 2; mi++) {
                ldsm4(Afh[mi][0], Afh[mi][1], Afh[mi][2], Afh[mi][3], kb + aoff[mi]);
                ldsm4(Afl[mi][0], Afl[mi][1], Afl[mi][2], Afl[mi][3],
                      kb + TILEB + aoff[mi]);
            }
            #pragma unroll
            for (int njp = 0; njp < 4; njp++) {
                uint32_t r0, r1, r2, r3;
                ldsm4(r0, r1, r2, r3, kb + 2 * TILEB + boff[njp]);
                Bfh[2 * njp][0] = r0; Bfh[2 * njp][1] = r1;
                Bfh[2 * njp + 1][0] = r2; Bfh[2 * njp + 1][1] = r3;
                ldsm4(r0, r1, r2, r3, kb + 3 * TILEB + boff[njp]);
                Bfl[2 * njp][0] = r0; Bfl[2 * njp][1] = r1;
                Bfl[2 * njp + 1][0] = r2; Bfl[2 * njp + 1][1] = r3;
            }
            #pragma unroll
            for (int mi = 0; mi < 2; mi++)
                #pragma unroll
                for (int nj = 0; nj < 8; nj++) {
                    mma16816(Cf[mi][nj], Afh[mi], Bfh[nj]);
                    mma16816(Cf[mi][nj], Afh[mi], Bfl[nj]);
                    mma16816(Cf[mi][nj], Afl[mi], Bfh[nj]);
                }
        }
        __syncthreads();
        if (ch + 2 < nch) load_chunk(ch + 2);
    }

    // ---- store S tile ----
    float* Cb = C_ + (size_t)b * HW * HW + (size_t)m0 * HW + n0;
    int r0 = wm * 32 + (lane >> 2);
    int c0 = wn * 64 + ((lane & 3) << 1);
    #pragma unroll
    for (int mi = 0; mi < 2; mi++)
        #pragma unroll
        for (int nj = 0; nj < 8; nj++) {
            int r = r0 + mi * 16, c = c0 + nj * 8;
            *(float2*)&Cb[(size_t)r * HW + c] =
                make_float2(Cf[mi][nj][0], Cf[mi][nj][1]);
            *(float2*)&Cb[(size_t)(r + 8) * HW + c] =
                make_float2(Cf[mi][nj][2], Cf[mi][nj][3]);
        }

    // ---- fused per-tile softmax partials (max, sumexp over 128 cols) ----
    __shared__ float sredm[128][2];
    __shared__ float sreds[128][2];
    float mx4[4];
    #pragma unroll
    for (int s = 0; s < 4; s++) {
        int mi = s >> 1, qb = (s & 1) * 2;
        float m = -1e30f;
        #pragma unroll
        for (int nj = 0; nj < 8; nj++)
            m = fmaxf(m, fmaxf(Cf[mi][nj][qb], Cf[mi][nj][qb + 1]));
        m = fmaxf(m, __shfl_xor_sync(~0u, m, 1));
        m = fmaxf(m, __shfl_xor_sync(~0u, m, 2));
        mx4[s] = m;
    }
    if ((lane & 3) == 0) {
        #pragma unroll
        for (int s = 0; s < 4; s++) {
            int rloc = r0 + (s >> 1) * 16 + (s & 1) * 8;
            sredm[rloc][wn] = mx4[s];
        }
    }
    __syncthreads();
    float rmx[4], sm4[4];
    #pragma unroll
    for (int s = 0; s < 4; s++) {
        int rloc = r0 + (s >> 1) * 16 + (s & 1) * 8;
        rmx[s] = fmaxf(sredm[rloc][0], sredm[rloc][1]);
        int mi = s >> 1, qb = (s & 1) * 2;
        float sum = 0.f;
        #pragma unroll
        for (int nj = 0; nj < 8; nj++)
            sum += __expf(Cf[mi][nj][qb] - rmx[s]) +
                   __expf(Cf[mi][nj][qb + 1] - rmx[s]);
        sum += __shfl_xor_sync(~0u, sum, 1);
        sum += __shfl_xor_sync(~0u, sum, 2);
        sm4[s] = sum;
    }
    if ((lane & 3) == 0) {
        #pragma unroll
        for (int s = 0; s < 4; s++) {
            int rloc = r0 + (s >> 1) * 16 + (s & 1) * 8;
            sreds[rloc][wn] = sm4[s];
        }
    }
    __syncthreads();
    if (wn == 0 && (lane & 3) == 0) {
        #pragma unroll
        for (int s = 0; s < 4; s++) {
            int rloc = r0 + (s >> 1) * 16 + (s & 1) * 8;
            size_t ix = ((size_t)b * HW + m0 + rloc) * 32 + blockIdx.x;
            g_tmax[ix] = rmx[s];
            g_tsum[ix] = sreds[rloc][0] + sreds[rloc][1];
        }
    }
}

// =====================================================================
// Combine per-tile partials: rmax = max_t m_t; rinv = 1/Σ s_t exp(m_t−M)
// =====================================================================
__global__ __launch_bounds__(256) void rowfin_kernel() {
    int row = blockIdx.x * 8 + (threadIdx.x >> 5);   // global (b*HW + q)
    int lane = threadIdx.x & 31;
    float m = g_tmax[(size_t)row * 32 + lane];
    float s = g_tsum[(size_t)row * 32 + lane];
    float M = m;
    #pragma unroll
    for (int o = 16; o; o >>= 1) M = fmaxf(M, __shfl_xor_sync(~0u, M, o));
    float v = s * __expf(m - M);
    #pragma unroll
    for (int o = 16; o; o >>= 1) v += __shfl_xor_sync(~0u, v, o);
    if (lane == 0) {
        g_rmax[row] = M;
        g_rinv[row] = 1.0f / v;
    }
}

// =====================================================================
// GEMM2 with fused softmax A-path, TWO n-tiles per block (128x256),
// 2-stage pipeline.
// =====================================================================
#define KLEN (HW / KSPLIT)          // 1024
#define STAGE2B (6 * TILEB)         // 61440
#define GSMEM2 (2 * STAGE2B)        // 122880

__global__ __launch_bounds__(256, 1) void gemm2_mma() {
    extern __shared__ char gsm[];
    uint32_t smb = smem_u32(gsm);
    int b = blockIdx.z / KSPLIT, slice = blockIdx.z % KSPLIT;
    int koff = slice * KLEN;
    int m0 = blockIdx.y * 128, n0 = blockIdx.x * 256;
    int tid = threadIdx.x, lane = tid & 31, wid = tid >> 5;
    int wm = wid & 3, wn = wid >> 2;

    // A (S) per-thread: row r, 16-col group cg
    int r = tid >> 1, cg = (tid & 1) * 16;
    const float* Arow = g_S + ((size_t)(b * HW + m0 + r)) * HW + koff + cg;
    float rmax = g_rmax[(size_t)b * HW + m0 + r];
    float rinv = g_rinv[(size_t)b * HW + m0 + r];
    uint32_t ah_dst = smb + (uint32_t)(r * PADH + cg) * 2u;

    const bf16* Bh = g_VBh + (size_t)b * 512 * HW + (size_t)n0 * HW + koff;
    const bf16* Bl = g_VBl + (size_t)b * 512 * HW + (size_t)n0 * HW + koff;

    float Cf[2][2][8][4];   // [ntile][mi][nj][q]
    #pragma unroll
    for (int nt = 0; nt < 2; nt++)
        #pragma unroll
        for (int mi = 0; mi < 2; mi++)
            #pragma unroll
            for (int nj = 0; nj < 8; nj++)
                #pragma unroll
                for (int q = 0; q < 4; q++) Cf[nt][mi][nj][q] = 0.f;

    uint32_t aoff[2], boff[4];
    #pragma unroll
    for (int mi = 0; mi < 2; mi++)
        aoff[mi] = ((uint32_t)(wm * 32 + mi * 16 + (lane & 15)) * PADH +
                    ((lane >> 4) << 3)) * 2u;
    #pragma unroll
    for (int njp = 0; njp < 4; njp++)
        boff[njp] = ((uint32_t)(wn * 64 + njp * 16 + (lane & 7) + ((lane >> 4) << 3)) * PADH +
                     (((lane >> 3) & 1) << 3)) * 2u;

    const int nch = KLEN >> 5;   // 32

    // B loader: 4 tiles (nt0 hi, nt0 lo, nt1 hi, nt1 lo), 2048 pieces
    auto loadB = [&](int ch) {
        int k0 = ch << 5;
        uint32_t dbase = smb + (uint32_t)(ch & 1) * STAGE2B + 2 * TILEB;
        #pragma unroll
        for (int t = 0; t < 8; t++) {
            int e = tid + (t << 8);
            int matq = e >> 9, rem = e & 511;   // matq: nt*2 + hl
            int nt = matq >> 1, hl = matq & 1;
            int row = rem >> 2, cc = rem & 3;
            const bf16* src = (hl ? Bl : Bh) + (size_t)(nt * 128 + row) * HW + k0 + cc * 8;
            cpa16(dbase + (uint32_t)matq * TILEB +
                      (uint32_t)(row * PADH) * 2u + cc * 16, src);
        }
        cpa_commit();
    };

    float4 pf[4];
    auto loadS = [&](int ch) {
        #pragma unroll
        for (int j = 0; j < 4; j++)
            pf[j] = *(const float4*)(Arow + (ch << 5) + j * 4);
    };
    auto storeA = [&](int st) {
        uint32_t h8[8], l8[8];
        #pragma unroll
        for (int j = 0; j < 4; j++) {
            float4 v = pf[j];
            float p0v = __expf(v.x - rmax) * rinv;
            float p1v = __expf(v.y - rmax) * rinv;
            float p2v = __expf(v.z - rmax) * rinv;
            float p3v = __expf(v.w - rmax) * rinv;
            bf16 h0, l0, h1, l1, h2, l2, h3, l3;
            split_bf(p0v, h0, l0); split_bf(p1v, h1, l1);
            split_bf(p2v, h2, l2); split_bf(p3v, h3, l3);
            h8[2 * j]     = pack_bf(h0, h1);
            h8[2 * j + 1] = pack_bf(h2, h3);
            l8[2 * j]     = pack_bf(l0, l1);
            l8[2 * j + 1] = pack_bf(l2, l3);
        }
        uint32_t dst = ah_dst + (uint32_t)st * STAGE2B;
        asm volatile("st.shared.v4.b32 [%0], {%1,%2,%3,%4};"
                     :: "r"(dst), "r"(h8[0]), "r"(h8[1]), "r"(h8[2]), "r"(h8[3]));
        asm volatile("st.shared.v4.b32 [%0], {%1,%2,%3,%4};"
                     :: "r"(dst + 16), "r"(h8[4]), "r"(h8[5]), "r"(h8[6]), "r"(h8[7]));
        asm volatile("st.shared.v4.b32 [%0], {%1,%2,%3,%4};"
                     :: "r"(dst + TILEB), "r"(l8[0]), "r"(l8[1]), "r"(l8[2]), "r"(l8[3]));
        asm volatile("st.shared.v4.b32 [%0], {%1,%2,%3,%4};"
                     :: "r"(dst + TILEB + 16), "r"(l8[4]), "r"(l8[5]), "r"(l8[6]), "r"(l8[7]));
    };

    loadS(0);
    loadB(0);
    for (int ch = 0; ch < nch; ch++) {
        if (ch + 1 < nch) loadB(ch + 1);
        storeA(ch & 1);
        if (ch + 1 < nch) loadS(ch + 1);
        if (ch + 1 < nch) asm volatile("cp.async.wait_group 1;");
        else              asm volatile("cp.async.wait_group 0;");
        __syncthreads();

        uint32_t sbase = smb + (uint32_t)(ch & 1) * STAGE2B;
        #pragma unroll
        for (int ks = 0; ks < 2; ks++) {
            uint32_t kb = sbase + (ks << 5);
            uint32_t Afh[2][4], Afl[2][4];
            #pragma unroll
            for (int mi = 0; mi < 2; mi++) {
                ldsm4(Afh[mi][0], Afh[mi][1], Afh[mi][2], Afh[mi][3], kb + aoff[mi]);
                ldsm4(Afl[mi][0], Afl[mi][1], Afl[mi][2], Afl[mi][3],
                      kb + TILEB + aoff[mi]);
            }
            #pragma unroll
            for (int nt = 0; nt < 2; nt++) {
                uint32_t bh_base = kb + (uint32_t)(2 + 2 * nt) * TILEB;
                uint32_t Bfh[8][2], Bfl[8][2];
                #pragma unroll
                for (int njp = 0; njp < 4; njp++) {
                    uint32_t q0, q1, q2, q3;
                    ldsm4(q0, q1, q2, q3, bh_base + boff[njp]);
                    Bfh[2 * njp][0] = q0; Bfh[2 * njp][1] = q1;
                    Bfh[2 * njp + 1][0] = q2; Bfh[2 * njp + 1][1] = q3;
                    ldsm4(q0, q1, q2, q3, bh_base + TILEB + boff[njp]);
                    Bfl[2 * njp][0] = q0; Bfl[2 * njp][1] = q1;
                    Bfl[2 * njp + 1][0] = q2; Bfl[2 * njp + 1][1] = q3;
                }
                #pragma unroll
                for (int mi = 0; mi < 2; mi++)
                    #pragma unroll
                    for (int nj = 0; nj < 8; nj++) {
                        mma16816(Cf[nt][mi][nj], Afh[mi], Bfh[nj]);
                        mma16816(Cf[nt][mi][nj], Afh[mi], Bfl[nj]);
                        mma16816(Cf[nt][mi][nj], Afl[mi], Bfh[nj]);
                    }
            }
        }
        __syncthreads();
    }

    int r0 = wm * 32 + (lane >> 2);
    int c0 = wn * 64 + ((lane & 3) << 1);
    #pragma unroll
    for (int nt = 0; nt < 2; nt++) {
        float* Cb = g_ms + ((size_t)slice * NB + b) * HW * 512 +
                    (size_t)m0 * 512 + n0 + nt * 128;
        #pragma unroll
        for (int mi = 0; mi < 2; mi++)
            #pragma unroll
            for (int nj = 0; nj < 8; nj++) {
                int rr = r0 + mi * 16, c = c0 + nj * 8;
                *(float2*)&Cb[(size_t)rr * 512 + c] =
                    make_float2(Cf[nt][mi][nj][0], Cf[nt][mi][nj][1]);
                *(float2*)&Cb[(size_t)(rr + 8) * 512 + c] =
                    make_float2(Cf[nt][mi][nj][2], Cf[nt][mi][nj][3]);
            }
    }
}

// =====================================================================
// Epilogue: sum KSPLIT partials of g_ms, transpose, final outputs.
// =====================================================================
#define EPSM (2 * 256 * 33 * 4)
__global__ __launch_bounds__(256) void epilogue_kernel(
    const float* __restrict__ content, float* __restrict__ out) {
    extern __shared__ float esm[];
    float* ms = esm;              // [256][33]
    float* ss = esm + 256 * 33;
    int p0 = blockIdx.x * 32, b = blockIdx.y;
    int tid = threadIdx.x, w = tid >> 5, lane = tid & 31;
    #pragma unroll
    for (int it = 0; it < 8; it++) {
        int e = tid + (it << 8);
        int row = e >> 6;            // 0..31
        int c4 = (e & 63) << 2;      // 0..252
        float4 mv = make_float4(0.f, 0.f, 0.f, 0.f);
        float4 sv = make_float4(0.f, 0.f, 0.f, 0.f);
        #pragma unroll
        for (int sl = 0; sl < KSPLIT; sl++) {
            const float* src = g_ms +
                (((size_t)sl * NB + b) * HW + p0 + row) * 512;
            float4 t = *(const float4*)(src + c4);
            float4 u = *(const float4*)(src + 256 + c4);
            mv.x += t.x; mv.y += t.y; mv.z += t.z; mv.w += t.w;
            sv.x += u.x; sv.y += u.y; sv.z += u.z; sv.w += u.w;
        }
        ms[(c4 + 0) * 33 + row] = mv.x; ms[(c4 + 1) * 33 + row] = mv.y;
        ms[(c4 + 2) * 33 + row] = mv.z; ms[(c4 + 3) * 33 + row] = mv.w;
        ss[(c4 + 0) * 33 + row] = sv.x; ss[(c4 + 1) * 33 + row] = sv.y;
        ss[(c4 + 2) * 33 + row] = sv.z; ss[(c4 + 3) * 33 + row] = sv.w;
    }
    __syncthreads();
    const size_t TSZ = (size_t)NB * CH * HW;
    #pragma unroll 4
    for (int g = 0; g < 32; g++) {
        int c = w * 32 + g;
        float mean = ms[c * 33 + lane];
        float sec  = ss[c * 33 + lane];
        float sd   = sqrtf(fmaxf(sec - mean * mean, 0.f));
        size_t idx = ((size_t)b * CH + c) * HW + p0 + lane;
        float nc = (content[idx] - g_mean[b * CH + c]) * g_rstd[b * CH + c];
        out[idx]           = sd * nc + mean;
        out[idx + TSZ]     = mean;
        out[idx + 2 * TSZ] = sd;
    }
}

// =====================================================================
extern "C" void kernel_launch(void* const* d_in, const int* in_sizes, int n_in,
                              void* d_out, int out_size) {
    const float* content = (const float*)d_in[0];
    const float* style   = (const float*)d_in[1];
    const float* Wf = (const float*)d_in[2];
    const float* bfp = (const float*)d_in[3];
    const float* Wg = (const float*)d_in[4];
    const float* bg = (const float*)d_in[5];
    const float* Wh = (const float*)d_in[6];
    const float* bh = (const float*)d_in[7];
    float* out = (float*)d_out;

    static bool init = false;
    static bf16 *pQh, *pQl, *pKh, *pKl;
    static float *pS;
    if (!init) {
        cudaGetSymbolAddress((void**)&pQh, g_Qh);
        cudaGetSymbolAddress((void**)&pQl, g_Ql);
        cudaGetSymbolAddress((void**)&pKh, g_Kh);
        cudaGetSymbolAddress((void**)&pKl, g_Kl);
        cudaGetSymbolAddress((void**)&pS, g_S);
        cudaFuncSetAttribute(mma_gemm,
                             cudaFuncAttributeMaxDynamicSharedMemorySize, GSMEM);
        cudaFuncSetAttribute(gemm2_mma,
                             cudaFuncAttributeMaxDynamicSharedMemorySize, GSMEM2);
        cudaFuncSetAttribute(epilogue_kernel,
                             cudaFuncAttributeMaxDynamicSharedMemorySize, EPSM);
        init = true;
    }

    stats_kernel<<<2 * NBC, 256>>>(content, style);
    qkv_gemm<<<dim3(HW / 128, CH / 64, 3 * NB), 256>>>(content, style,
                                                       Wf, bfp, Wg, bg, Wh, bh);
    // GEMM1: S = Qn . Kn^T + fused per-tile softmax partials
    mma_gemm<<<dim3(HW / 128, HW / 128, NB), 256, GSMEM>>>(
        pQh, pQl, pKh, pKl, pS);
    rowfin_kernel<<<NB * HW / 8, 256>>>();
    // GEMM2: [mean|sec] = softmax(S) . [V^T ; V2^T]^T, fused exp A-path,
    // two n-tiles per block (A converted once, reused); 128x256 blocks.
    gemm2_mma<<<dim3(512 / 256, HW / 128, NB * KSPLIT), 256, GSMEM2>>>();
    epilogue_kernel<<<dim3(HW / 32, NB), 256, EPSM>>>(content, out);
}